// round 15
// baseline (speedup 1.0000x reference)
#include <cuda_runtime.h>
#include <cuda_bf16.h>
#include <cstdint>

// Problem dims (fixed by dataset)
#define NN    8192
#define DD    512
#define HTOT  2048   // P*H = 8*256 stacked perspectives
#define HID   256
#define CC    64
#define TOPK  30

using bf16 = __nv_bfloat16;

// tcgen05 is only legal in the compute_103a device pass. The harness also
// compiles a plain sm_103 pass; give it a correct fallback body.
#if defined(__CUDA_ARCH__) && !defined(__CUDA_ARCH_FEAT_SM103_ALL)
#define TC_FALLBACK 1
#else
#define TC_FALLBACK 0
#endif

// -------- scratch (static device globals; no allocation allowed) ----------
__device__ bf16  g_fA_hi[(size_t)NN * DD];
__device__ bf16  g_fA_lo[(size_t)NN * DD];
__device__ bf16  g_fX_hi[(size_t)NN * DD];
__device__ bf16  g_fX_lo[(size_t)NN * DD];
__device__ bf16  g_fW_hi[(size_t)HTOT * DD];
__device__ bf16  g_fW_lo[(size_t)HTOT * DD];
__device__ bf16  g_W1_hi[(size_t)HID * DD];
__device__ bf16  g_W1_lo[(size_t)HID * DD];
__device__ bf16  g_Hh[(size_t)NN * HTOT];
__device__ bf16  g_Hl[(size_t)NN * HTOT];
__device__ float g_hidden[(size_t)NN * HID];
__device__ float g_h[(size_t)NN * HID];
__device__ float g_g[(size_t)NN * CC];
__device__ int   g_idx[(size_t)NN * TOPK];
__device__ float g_w[(size_t)NN * TOPK];

// ===========================================================================
// PTX helpers
// ===========================================================================
__device__ __forceinline__ uint32_t smem_to_u32(const void* p) {
    uint32_t a;
    asm("{ .reg .u64 t; cvta.to.shared.u64 t, %1; cvt.u32.u64 %0, t; }" : "=r"(a) : "l"(p));
    return a;
}
__device__ __forceinline__ uint32_t elect_one_pred() {
    uint32_t p;
    asm volatile("{ .reg .pred p; elect.sync _|p, 0xFFFFFFFF; selp.b32 %0, 1, 0, p; }" : "=r"(p));
    return p;
}

#define TCGEN05_ALLOC(sa, n) \
    asm volatile("tcgen05.alloc.cta_group::1.sync.aligned.shared::cta.b32 [%0], %1;" \
        :: "r"((uint32_t)(sa)), "r"((uint32_t)(n)) : "memory")
#define TCGEN05_DEALLOC(t, n) \
    asm volatile("tcgen05.dealloc.cta_group::1.sync.aligned.b32 %0, %1;" :: "r"(t), "r"((uint32_t)(n)))
#define TCGEN05_RELINQ() \
    asm volatile("tcgen05.relinquish_alloc_permit.cta_group::1.sync.aligned;")
#define TCGEN05_COMMIT(mb) \
    asm volatile("tcgen05.commit.cta_group::1.mbarrier::arrive::one.shared::cluster.b64 [%0];" \
        :: "r"((uint32_t)(mb)) : "memory")
#define TCGEN05_WAIT_LD()  asm volatile("tcgen05.wait::ld.sync.aligned;" ::: "memory")
#define TCGEN05_FENCE_AFTER()  asm volatile("tcgen05.fence::after_thread_sync;" ::: "memory")
#define TCGEN05_FENCE_BEFORE() asm volatile("tcgen05.fence::before_thread_sync;" ::: "memory")

#define MBARRIER_INIT(mb, c) \
    asm volatile("mbarrier.init.shared.b64 [%0], %1;" :: "r"((uint32_t)(mb)), "r"((uint32_t)(c)) : "memory")
#define MBARRIER_INVAL(mb) \
    asm volatile("mbarrier.inval.shared.b64 [%0];" :: "r"((uint32_t)(mb)) : "memory")

#define MBARRIER_WAIT_PARITY(mb, ph) do { \
    uint32_t _mb = (uint32_t)(mb), _ph = (uint32_t)(ph), _done; \
    asm volatile("{ .reg .pred p; mbarrier.try_wait.parity.acquire.cta.shared::cta.b64 p, [%1], %2; selp.b32 %0, 1, 0, p; }" \
        : "=r"(_done) : "r"(_mb), "r"(_ph) : "memory"); \
    if (!_done) { \
        asm volatile("{ .reg .pred P1; WL_%=: mbarrier.try_wait.parity.acquire.cta.shared::cta.b64 P1, [%0], %1, 0x989680; @P1 bra.uni WD_%=; bra.uni WL_%=; WD_%=: }" \
            :: "r"(_mb), "r"(_ph) : "memory"); \
    } } while (0)

#define TCGEN05_LD_32X32B_X32(r, ta) \
    asm volatile( \
        "tcgen05.ld.sync.aligned.32x32b.x32.b32 " \
        "{%0, %1, %2, %3, %4, %5, %6, %7, " \
        " %8, %9, %10, %11, %12, %13, %14, %15, " \
        " %16, %17, %18, %19, %20, %21, %22, %23, " \
        " %24, %25, %26, %27, %28, %29, %30, %31}, [%32];" \
        : "=r"((r)[0]),  "=r"((r)[1]),  "=r"((r)[2]),  "=r"((r)[3]), \
          "=r"((r)[4]),  "=r"((r)[5]),  "=r"((r)[6]),  "=r"((r)[7]), \
          "=r"((r)[8]),  "=r"((r)[9]),  "=r"((r)[10]), "=r"((r)[11]), \
          "=r"((r)[12]), "=r"((r)[13]), "=r"((r)[14]), "=r"((r)[15]), \
          "=r"((r)[16]), "=r"((r)[17]), "=r"((r)[18]), "=r"((r)[19]), \
          "=r"((r)[20]), "=r"((r)[21]), "=r"((r)[22]), "=r"((r)[23]), \
          "=r"((r)[24]), "=r"((r)[25]), "=r"((r)[26]), "=r"((r)[27]), \
          "=r"((r)[28]), "=r"((r)[29]), "=r"((r)[30]), "=r"((r)[31]) \
        : "r"(ta))

#define CP_ASYNC16(dst, src) \
    asm volatile("cp.async.cg.shared.global [%0], [%1], 16;" :: "r"(dst), "l"(src) : "memory")
#define CP_COMMIT() asm volatile("cp.async.commit_group;" ::: "memory")
#define CP_WAIT(n)  asm volatile("cp.async.wait_group %0;" :: "n"(n) : "memory")

// SW64 smem descriptor: layout=SW64(4), version=1(Blackwell), SBO=32, LBO=1
// (atom = 8 rows x 64 bytes; exact fit for 32-col bf16 rows)
static constexpr uint64_t SMEM_DESC_BASE_SW64 =
    (uint64_t(4) << 61) | (uint64_t(1) << 46) | (uint64_t(32) << 32) | (uint64_t(1) << 16);
#define MAKE_SMEM_DESC64(a) (SMEM_DESC_BASE_SW64 | ((uint64_t)((a) >> 4) & 0x3FFF))

#if !TC_FALLBACK
// SS bf16 MMA, cta_group::1, fp32 accumulate
__device__ __forceinline__ void mma_bf16_ss_cg1(uint32_t d, uint64_t ad, uint64_t bd,
                                                uint32_t idesc, bool accum) {
    uint32_t en = accum ? 1u : 0u;
    asm volatile(
        "{\n\t.reg .pred p;\n\tsetp.ne.u32 p, %5, 0;\n\t"
        "tcgen05.mma.cta_group::1.kind::f16 [%0], %1, %2, %3, {%4, %4, %4, %4}, p;\n\t}"
        :: "r"(d), "l"(ad), "l"(bd), "r"(idesc), "r"(0u), "r"(en) : "memory");
}
#endif

// ===========================================================================
// fused dual fp32 -> (bf16 hi, bf16 lo) split (one launch for two tensors)
// ===========================================================================
__device__ __forceinline__ void split_body(const float* __restrict__ in,
                                           bf16* __restrict__ hi, bf16* __restrict__ lo,
                                           int i)
{
    float4 v = *(const float4*)(in + i);
    float vv[4] = {v.x, v.y, v.z, v.w};
    bf16 h[4], l[4];
#pragma unroll
    for (int j = 0; j < 4; j++) {
        bf16 hh = __float2bfloat16(vv[j]);
        h[j] = hh;
        l[j] = __float2bfloat16(vv[j] - __bfloat162float(hh));
    }
    *(uint2*)(hi + i) = *(uint2*)h;
    *(uint2*)(lo + i) = *(uint2*)l;
}

__global__ void split2_kernel(const float* __restrict__ in1, bf16* __restrict__ hi1,
                              bf16* __restrict__ lo1, int n1,
                              const float* __restrict__ in2, bf16* __restrict__ hi2,
                              bf16* __restrict__ lo2, int n2)
{
    int i = (blockIdx.x * blockDim.x + threadIdx.x) * 4;
    if (i < n1) { split_body(in1, hi1, lo1, i); return; }
    i -= n1;
    if (i < n2) split_body(in2, hi2, lo2, i);
}

// ===========================================================================
// tcgen05 bf16x3 NT GEMM, 128x256 tile, K-chunk 32 (SW64 atoms),
// 2-stage cp.async pipeline AND 2 CTAs/SM (permit relinquished at alloc).
// MODE 0: C = relu(A B^T), output split to bf16 hi/lo (Chi/Clo)
// MODE 1: syrk tiles (bi <= 2*bj+1), C = scale*A A^T fp32
// MODE 2: C = A B^T + bias, fp32
// ===========================================================================
#define KCC   32
#define NT    256
#define STAGE 49152          // Ah 8K | Al 8K | Bh 16K | Bl 16K
#define OFF_AH 0
#define OFF_AL 8192
#define OFF_BH 16384
#define OFF_BL 32768
#define SMEM_TOTAL2 (1024 + 2 * STAGE)
// idesc: dtype F32, atype/btype BF16, N=256 (32<<17), M=128 (8<<24)
#define TC_IDESC2 ((1u << 4) | (1u << 7) | (1u << 10) | (32u << 17) | (8u << 24))

#if !TC_FALLBACK
// cp.async one K-chunk (32 cols = 64B rows, SW64): A 128 rows, B 256 rows.
__device__ __forceinline__ void load_chunk_ca(const bf16* __restrict__ Arh,
                                              const bf16* __restrict__ Arl,
                                              const bf16* __restrict__ Brh,
                                              const bf16* __restrict__ Brl,
                                              int ldk, int k0, uint32_t st, int tid)
{
#pragma unroll
    for (int g = tid; g < 512; g += 256) {       // 128 rows x 4 granules
        int row = g >> 2;
        int gc  = g & 3;                          // 16B granule within 64B row
        size_t go = (size_t)row * ldk + k0 + gc * 8;
        uint32_t boff = (uint32_t)((row >> 3) * 512 + (row & 7) * 64 + gc * 16);
        uint32_t sw = boff ^ ((boff >> 3) & 0x30u);
        CP_ASYNC16(st + OFF_AH + sw, Arh + go);
        CP_ASYNC16(st + OFF_AL + sw, Arl + go);
    }
#pragma unroll
    for (int g = tid; g < 1024; g += 256) {      // 256 rows x 4 granules
        int row = g >> 2;
        int gc  = g & 3;
        size_t go = (size_t)row * ldk + k0 + gc * 8;
        uint32_t boff = (uint32_t)((row >> 3) * 512 + (row & 7) * 64 + gc * 16);
        uint32_t sw = boff ^ ((boff >> 3) & 0x30u);
        CP_ASYNC16(st + OFF_BH + sw, Brh + go);
        CP_ASYNC16(st + OFF_BL + sw, Brl + go);
    }
}
#endif

template<int MODE>
__global__ __launch_bounds__(256, 2)
void tc_gemm_kernel(const bf16* __restrict__ Ah, const bf16* __restrict__ Al,
                    const bf16* __restrict__ Bh, const bf16* __restrict__ Bl,
                    float* __restrict__ Cf, bf16* __restrict__ Chi, bf16* __restrict__ Clo,
                    const float* __restrict__ bias,
                    int Mdim, int Ndim, int Kdim, float scale)
{
    extern __shared__ char smem[];
    const int tid = threadIdx.x;

    int bm, bn, bi = 0, bj = 0;
    if (MODE == 1) {
        int t = blockIdx.x;
        for (;;) {
            int cnt = 2 * bj + 2; if (cnt > 64) cnt = 64;
            if (t < cnt) break;
            t -= cnt; bj++;
        }
        bi = t;
        bm = bi * 128; bn = bj * NT;
    } else {
        bm = blockIdx.y * 128; bn = blockIdx.x * NT;
    }

#if TC_FALLBACK
    // ------- plain-sm_103 pass: correct, slow FFMA path (dead code on GB300) ---
    (void)smem;
    const bool straddle = (MODE == 1) && (bi >= 2 * bj);
    const int tm = (tid >> 4) << 3;
    const int tnb = (tid & 15) << 3;
    for (int nh = 0; nh < 2; nh++) {
        int tn = nh * 128 + tnb;
        float acc[8][8];
#pragma unroll
        for (int i = 0; i < 8; i++)
#pragma unroll
            for (int j = 0; j < 8; j++) acc[i][j] = 0.f;
        for (int k = 0; k < Kdim; k++) {
            float a[8], b[8];
#pragma unroll
            for (int i = 0; i < 8; i++) {
                size_t o = (size_t)(bm + tm + i) * Kdim + k;
                a[i] = __bfloat162float(Ah[o]) + __bfloat162float(Al[o]);
            }
#pragma unroll
            for (int j = 0; j < 8; j++) {
                size_t o = (size_t)(bn + tn + j) * Kdim + k;
                b[j] = __bfloat162float(Bh[o]) + __bfloat162float(Bl[o]);
            }
#pragma unroll
            for (int i = 0; i < 8; i++)
#pragma unroll
                for (int j = 0; j < 8; j++)
                    acc[i][j] = fmaf(a[i], b[j], acc[i][j]);
        }
#pragma unroll
        for (int i = 0; i < 8; i++) {
            int gr = bm + tm + i;
#pragma unroll
            for (int j = 0; j < 8; j++) {
                int gc = bn + tn + j;
                float v = acc[i][j];
                if (MODE == 0) {
                    v = fmaxf(v, 0.f);
                    bf16 hh = __float2bfloat16(v);
                    Chi[(size_t)gr * Ndim + gc] = hh;
                    Clo[(size_t)gr * Ndim + gc] = __float2bfloat16(v - __bfloat162float(hh));
                } else if (MODE == 2) {
                    Cf[(size_t)gr * Ndim + gc] = v + bias[gc];
                } else {
                    v *= scale;
                    if (!straddle || gc >= gr) Cf[(size_t)gr * Ndim + gc] = v;
                    if (gc > gr)               Cf[(size_t)gc * Ndim + gr] = v;
                }
            }
        }
    }
#else
    // ------- sm_103a pass: tcgen05 bf16x3, 2-stage + 2 CTAs/SM -------
    const uint32_t sb = smem_to_u32(smem);
    const int wid = tid >> 5;
    const int lid = tid & 31;

    if (wid == 0) {
        TCGEN05_ALLOC(sb + 0, 256);
        TCGEN05_RELINQ();          // free permit immediately (R13 fix)
    }
    if (tid == 0) { MBARRIER_INIT(sb + 8, 1); MBARRIER_INIT(sb + 16, 1); }
    __syncthreads();
    uint32_t tmem;
    asm volatile("ld.shared.b32 %0, [%1];" : "=r"(tmem) : "r"(sb));

    const bf16* Arh = Ah + (size_t)bm * Kdim;
    const bf16* Arl = Al + (size_t)bm * Kdim;
    const bf16* Brh = Bh + (size_t)bn * Kdim;
    const bf16* Brl = Bl + (size_t)bn * Kdim;

    const uint32_t st0 = sb + 1024;
    int ph[2] = {0, 0};
    const int nc = Kdim / KCC;

    // prefetch chunk 0 into stage 0
    load_chunk_ca(Arh, Arl, Brh, Brl, Kdim, 0, st0, tid);
    CP_COMMIT();

    for (int c = 0; c < nc; c++) {
        const int s = c & 1;
        if (c + 1 < nc) {
            const int o = 1 - s;
            if (c >= 1) {
                // stage o was consumed by MMA of chunk c-1; wait its completion
                MBARRIER_WAIT_PARITY(sb + 8 + 8 * o, ph[o]); ph[o] ^= 1;
            }
            load_chunk_ca(Arh, Arl, Brh, Brl, Kdim, (c + 1) * KCC, st0 + o * STAGE, tid);
            CP_COMMIT();
            CP_WAIT(1);          // chunk c's loads complete
        } else {
            CP_WAIT(0);
        }
        asm volatile("fence.proxy.async.shared::cta;" ::: "memory");
        __syncthreads();
        if (wid == 0 && elect_one_pred()) {
            const uint32_t so = st0 + s * STAGE;
            const uint64_t dAh = MAKE_SMEM_DESC64(so + OFF_AH);
            const uint64_t dAl = MAKE_SMEM_DESC64(so + OFF_AL);
            const uint64_t dBh = MAKE_SMEM_DESC64(so + OFF_BH);
            const uint64_t dBl = MAKE_SMEM_DESC64(so + OFF_BL);
#pragma unroll
            for (int ks = 0; ks < 2; ks++) {
                const uint64_t off = 2 * ks;      // 32B per K16 step within atom
                mma_bf16_ss_cg1(tmem, dAh + off, dBh + off, TC_IDESC2, !(c == 0 && ks == 0));
                mma_bf16_ss_cg1(tmem, dAh + off, dBl + off, TC_IDESC2, true);
                mma_bf16_ss_cg1(tmem, dAl + off, dBh + off, TC_IDESC2, true);
            }
            TCGEN05_COMMIT(sb + 8 + 8 * s);
        }
    }
    // drain: MMAs complete in order; wait chunk nc-2 then nc-1
    {
        int s = (nc - 2) & 1;
        MBARRIER_WAIT_PARITY(sb + 8 + 8 * s, ph[s]); ph[s] ^= 1;
        s = (nc - 1) & 1;
        MBARRIER_WAIT_PARITY(sb + 8 + 8 * s, ph[s]); ph[s] ^= 1;
    }
    TCGEN05_FENCE_AFTER();

    // Epilogue: warps 0-3 read the 128x256 fp32 accumulator (lane = M-row)
    if (wid < 4) {
        const int row = bm + wid * 32 + lid;
        const bool straddle = (MODE == 1) && (bi >= 2 * bj);
#pragma unroll
        for (int cb = 0; cb < 8; cb++) {
            uint32_t r[32];
            TCGEN05_LD_32X32B_X32(r, tmem + cb * 32);
            TCGEN05_WAIT_LD();
            const int colb = bn + cb * 32;
            if (MODE == 0) {
#pragma unroll
                for (int c8 = 0; c8 < 4; c8++) {
                    bf16 hs[8], ls[8];
#pragma unroll
                    for (int j = 0; j < 8; j++) {
                        float v = fmaxf(__uint_as_float(r[c8 * 8 + j]), 0.f);
                        bf16 hh = __float2bfloat16(v);
                        hs[j] = hh;
                        ls[j] = __float2bfloat16(v - __bfloat162float(hh));
                    }
                    size_t o = (size_t)row * Ndim + colb + c8 * 8;
                    *(uint4*)(Chi + o) = *(uint4*)hs;
                    *(uint4*)(Clo + o) = *(uint4*)ls;
                }
            } else if (MODE == 2) {
#pragma unroll
                for (int q = 0; q < 8; q++) {
                    float4 o;
                    o.x = __uint_as_float(r[q * 4 + 0]) + bias[colb + q * 4 + 0];
                    o.y = __uint_as_float(r[q * 4 + 1]) + bias[colb + q * 4 + 1];
                    o.z = __uint_as_float(r[q * 4 + 2]) + bias[colb + q * 4 + 2];
                    o.w = __uint_as_float(r[q * 4 + 3]) + bias[colb + q * 4 + 3];
                    *(float4*)(Cf + (size_t)row * Ndim + colb + q * 4) = o;
                }
            } else {
                float vs[32];
#pragma unroll
                for (int c = 0; c < 32; c++) vs[c] = __uint_as_float(r[c]) * scale;
                if (!straddle) {
                    float* dst = Cf + (size_t)row * Ndim + colb;
#pragma unroll
                    for (int q = 0; q < 8; q++)
                        *(float4*)(dst + q * 4) =
                            make_float4(vs[q * 4], vs[q * 4 + 1], vs[q * 4 + 2], vs[q * 4 + 3]);
#pragma unroll
                    for (int c = 0; c < 32; c++)
                        Cf[(size_t)(colb + c) * Ndim + row] = vs[c];
                } else {
#pragma unroll
                    for (int c = 0; c < 32; c++) {
                        const int gc = colb + c;
                        if (gc >= row) Cf[(size_t)row * Ndim + gc] = vs[c];
                        if (gc > row)  Cf[(size_t)gc * Ndim + row] = vs[c];
                    }
                }
            }
        }
        TCGEN05_FENCE_BEFORE();
    }
    __syncthreads();
    if (tid == 0) { MBARRIER_INVAL(sb + 8); MBARRIER_INVAL(sb + 16); }
    __syncthreads();
    if (wid == 0) TCGEN05_DEALLOC(tmem, 256);
#endif
}

// ===========================================================================
// SIMT fp32 NT GEMM (kept for the tiny h @ W2^T + b2)
// ===========================================================================
#define TILE 128
#define KT   16
#define SPITCH 130
template<int RELU, int BIAS>
__global__ __launch_bounds__(256)
void gemm_nt_kernel(const float* __restrict__ A, const float* __restrict__ B,
                    const float* __restrict__ bias, float* __restrict__ C,
                    int M, int N, int K)
{
    __shared__ float As[KT][SPITCH];
    __shared__ float Bs[KT][SPITCH];
    const int tid = threadIdx.x;
    const int bm = blockIdx.y * TILE;
    const int bn = blockIdx.x * TILE;
    const int tm = (tid >> 4) << 3;
    const int tn = (tid & 15) << 3;

    float acc[8][8];
#pragma unroll
    for (int i = 0; i < 8; i++)
#pragma unroll
        for (int j = 0; j < 8; j++) acc[i][j] = 0.f;

    const int lrow  = tid >> 1;
    const int lhalf = (tid & 1) * 8;

    for (int k0 = 0; k0 < K; k0 += KT) {
        {
            int gr = bm + lrow;
            float4 v0 = make_float4(0, 0, 0, 0), v1 = v0;
            if (gr < M) {
                const float* src = A + (size_t)gr * K + k0 + lhalf;
                v0 = *(const float4*)src; v1 = *(const float4*)(src + 4);
            }
            As[lhalf+0][lrow]=v0.x; As[lhalf+1][lrow]=v0.y;
            As[lhalf+2][lrow]=v0.z; As[lhalf+3][lrow]=v0.w;
            As[lhalf+4][lrow]=v1.x; As[lhalf+5][lrow]=v1.y;
            As[lhalf+6][lrow]=v1.z; As[lhalf+7][lrow]=v1.w;
        }
        {
            int gr = bn + lrow;
            float4 v0 = make_float4(0, 0, 0, 0), v1 = v0;
            if (gr < N) {
                const float* src = B + (size_t)gr * K + k0 + lhalf;
                v0 = *(const float4*)src; v1 = *(const float4*)(src + 4);
            }
            Bs[lhalf+0][lrow]=v0.x; Bs[lhalf+1][lrow]=v0.y;
            Bs[lhalf+2][lrow]=v0.z; Bs[lhalf+3][lrow]=v0.w;
            Bs[lhalf+4][lrow]=v1.x; Bs[lhalf+5][lrow]=v1.y;
            Bs[lhalf+6][lrow]=v1.z; Bs[lhalf+7][lrow]=v1.w;
        }
        __syncthreads();
#pragma unroll
        for (int kk = 0; kk < KT; kk++) {
            float a[8], b[8];
#pragma unroll
            for (int i = 0; i < 8; i++) a[i] = As[kk][tm + i];
#pragma unroll
            for (int j = 0; j < 8; j++) b[j] = Bs[kk][tn + j];
#pragma unroll
            for (int i = 0; i < 8; i++)
#pragma unroll
                for (int j = 0; j < 8; j++)
                    acc[i][j] = fmaf(a[i], b[j], acc[i][j]);
        }
        __syncthreads();
    }
#pragma unroll
    for (int i = 0; i < 8; i++) {
        int gr = bm + tm + i;
        if (gr >= M) break;
#pragma unroll
        for (int j = 0; j < 8; j++) {
            int gc = bn + tn + j;
            if (gc < N) {
                float v = acc[i][j];
                if (BIAS) v += bias[gc];
                if (RELU) v = fmaxf(v, 0.f);
                C[(size_t)gr * N + gc] = v;
            }
        }
    }
}

// ===========================================================================
// Per-row top-30 + softmax via 4-round radix select (proven R11)
// ===========================================================================
__global__ __launch_bounds__(256)
void topk_softmax_kernel(float* __restrict__ adj,
                         int* __restrict__ oidx, float* __restrict__ ow)
{
    const int row = blockIdx.x;
    const int tid = threadIdx.x;
    float* rp = adj + (size_t)row * NN;

    uint32_t u[32];
#pragma unroll
    for (int i = 0; i < 32; i++) {
        uint32_t b = __float_as_uint(rp[tid + 256 * i]);
        u[i] = (b & 0x80000000u) ? ~b : (b | 0x80000000u);
    }

    __shared__ uint32_t hist[256];
    __shared__ uint32_t sS[256];
    __shared__ uint32_t sb_sel, sAboveSh;
    __shared__ int swin, snsel;
    __shared__ int   scol[TOPK];
    __shared__ float sval[TOPK];
    __shared__ int   warpmin[8];
    __shared__ float se[32];
    __shared__ float sinv;

    uint32_t pref = 0;
    uint32_t above = 0;
    int shift = 24;

#pragma unroll
    for (int round = 0; round < 4; round++) {
        hist[tid] = 0;
        __syncthreads();
        if (round == 0) {
#pragma unroll
            for (int i = 0; i < 32; i++)
                atomicAdd(&hist[u[i] >> 24], 1u);
        } else {
            const uint32_t mask = 0xFFFFFFFFu << (shift + 8);
#pragma unroll
            for (int i = 0; i < 32; i++)
                if ((u[i] & mask) == pref)
                    atomicAdd(&hist[(u[i] >> shift) & 255u], 1u);
        }
        __syncthreads();
        sS[tid] = hist[tid];
        for (int off = 1; off < 256; off <<= 1) {
            __syncthreads();
            uint32_t t = (tid + off < 256) ? sS[tid + off] : 0u;
            __syncthreads();
            sS[tid] += t;
        }
        __syncthreads();
        {
            uint32_t gt = above + ((tid < 255) ? sS[tid + 1] : 0u);
            uint32_t ge = above + sS[tid];
            if (gt < TOPK && ge >= TOPK) { sb_sel = (uint32_t)tid; sAboveSh = gt; }
        }
        __syncthreads();
        pref |= sb_sel << shift;
        above = sAboveSh;
        shift -= 8;
        __syncthreads();
    }

    const uint32_t T = pref;
    const int tcount = TOPK - (int)above;
    uint32_t tb = (T & 0x80000000u) ? (T ^ 0x80000000u) : ~T;
    const float Tf = __uint_as_float(tb);

    if (tid == 0) snsel = 0;
    __syncthreads();
#pragma unroll
    for (int i = 0; i < 32; i++) {
        if (u[i] > T) {
            int s = atomicAdd(&snsel, 1);
            scol[s] = tid + 256 * i;
            uint32_t k = u[i];
            uint32_t vb = (k & 0x80000000u) ? (k ^ 0x80000000u) : ~k;
            sval[s] = __uint_as_float(vb);
        }
    }
    __syncthreads();

    uint32_t takenMask = 0;
    for (int t = 0; t < tcount; t++) {
        int mc = 0x7FFFFFFF;
#pragma unroll
        for (int i = 0; i < 32; i++)
            if (u[i] == T && !(takenMask & (1u << i))) {
                int c = tid + 256 * i;
                if (c < mc) mc = c;
            }
#pragma unroll
        for (int s = 16; s; s >>= 1) {
            int o = __shfl_down_sync(0xFFFFFFFFu, mc, s);
            if (o < mc) mc = o;
        }
        if ((tid & 31) == 0) warpmin[tid >> 5] = mc;
        __syncthreads();
        if (tid == 0) {
            int m = warpmin[0];
#pragma unroll
            for (int w = 1; w < 8; w++) if (warpmin[w] < m) m = warpmin[w];
            swin = m;
            int s = snsel;
            scol[s] = m; sval[s] = Tf; snsel = s + 1;
        }
        __syncthreads();
        int w = swin;
        if ((w & 255) == tid) takenMask |= 1u << (w >> 8);
    }
    __syncthreads();

    if (tid < 32) {
        float v = (tid < TOPK) ? sval[tid] : -3.4e38f;
        float m = v;
#pragma unroll
        for (int s = 16; s; s >>= 1) m = fmaxf(m, __shfl_xor_sync(0xFFFFFFFFu, m, s));
        float e = (tid < TOPK) ? expf(v - m) : 0.f;
        se[tid] = e;
#pragma unroll
        for (int s = 16; s; s >>= 1) e += __shfl_down_sync(0xFFFFFFFFu, e, s);
        if (tid == 0) sinv = 1.f / e;
    }
    __syncthreads();

    float4 z = make_float4(0.f, 0.f, 0.f, 0.f);
    float4* rp4 = (float4*)rp;
#pragma unroll
    for (int i = 0; i < 8; i++) rp4[tid + 256 * i] = z;
    __syncthreads();
    if (tid < TOPK) {
        float wv = se[tid] * sinv;
        rp[scol[tid]] = wv;
        oidx[(size_t)row * TOPK + tid] = scol[tid];
        ow[(size_t)row * TOPK + tid] = wv;
    }
}

// ===========================================================================
// Sparse adj @ M
// ===========================================================================
template<int RELU>
__global__ void spmm_kernel(const int* __restrict__ idx, const float* __restrict__ w,
                            const float* __restrict__ Min, float* __restrict__ Mout,
                            int ncols)
{
    const int row = blockIdx.x;
    const int j = threadIdx.x;
    const int*   ip = idx + (size_t)row * TOPK;
    const float* wp = w   + (size_t)row * TOPK;
    float acc = 0.f;
#pragma unroll
    for (int k = 0; k < TOPK; k++)
        acc = fmaf(wp[k], Min[(size_t)ip[k] * ncols + j], acc);
    if (RELU) acc = fmaxf(acc, 0.f);
    Mout[(size_t)row * ncols + j] = acc;
}

// ===========================================================================
extern "C" void kernel_launch(void* const* d_in, const int* in_sizes, int n_in,
                              void* d_out, int out_size)
{
    const float* features = (const float*)d_in[0];
    const float* x        = (const float*)d_in[1];
    const float* W_sims   = (const float*)d_in[2];
    const float* W1       = (const float*)d_in[3];
    const float* b1       = (const float*)d_in[4];
    const float* W2       = (const float*)d_in[5];
    const float* b2       = (const float*)d_in[6];

    float* out = (float*)d_out;
    float* adj = out + (size_t)NN * CC;

    bf16 *fAh, *fAl, *fXh, *fXl, *fWh, *fWl, *W1h, *W1l, *Hh, *Hl;
    float *hidden, *h, *g, *wv; int* idx;
    cudaGetSymbolAddress((void**)&fAh, g_fA_hi);  cudaGetSymbolAddress((void**)&fAl, g_fA_lo);
    cudaGetSymbolAddress((void**)&fXh, g_fX_hi);  cudaGetSymbolAddress((void**)&fXl, g_fX_lo);
    cudaGetSymbolAddress((void**)&fWh, g_fW_hi);  cudaGetSymbolAddress((void**)&fWl, g_fW_lo);
    cudaGetSymbolAddress((void**)&W1h, g_W1_hi);  cudaGetSymbolAddress((void**)&W1l, g_W1_lo);
    cudaGetSymbolAddress((void**)&Hh,  g_Hh);     cudaGetSymbolAddress((void**)&Hl,  g_Hl);
    cudaGetSymbolAddress((void**)&hidden, g_hidden);
    cudaGetSymbolAddress((void**)&h,  g_h);
    cudaGetSymbolAddress((void**)&g,  g_g);
    cudaGetSymbolAddress((void**)&wv, g_w);
    cudaGetSymbolAddress((void**)&idx, g_idx);

    cudaFuncSetAttribute(tc_gemm_kernel<0>, cudaFuncAttributeMaxDynamicSharedMemorySize, SMEM_TOTAL2);
    cudaFuncSetAttribute(tc_gemm_kernel<1>, cudaFuncAttributeMaxDynamicSharedMemorySize, SMEM_TOTAL2);
    cudaFuncSetAttribute(tc_gemm_kernel<2>, cudaFuncAttributeMaxDynamicSharedMemorySize, SMEM_TOTAL2);

    // Launch order puts the SYRK at our 4th launch (ncu -s 5 lands on it).

    // 0) fused split: features + W_sims
    {
        int n1 = NN * DD, n2 = HTOT * DD;
        split2_kernel<<<((n1 + n2) / 4 + 255) / 256, 256>>>(
            features, fAh, fAl, n1, W_sims, fWh, fWl, n2);
    }

    // 1) Hc = relu(X @ W_all^T), output re-split to bf16 hi/lo  [8192, 2048]
    tc_gemm_kernel<0><<<dim3(HTOT / NT, NN / 128), 256, SMEM_TOTAL2>>>(
        fAh, fAl, fWh, fWl, nullptr, Hh, Hl, nullptr, NN, HTOT, DD, 1.f);

    // 2) fused split: x + W1 (independent; placed here so syrk is 4th)
    {
        int n1 = NN * DD, n2 = HID * DD;
        split2_kernel<<<((n1 + n2) / 4 + 255) / 256, 256>>>(
            x, fXh, fXl, n1, W1, W1h, W1l, n2);
    }

    // 3) att = Hc Hc^T / 8  (128x256 tiles, bi<=2bj+1; 1056 tiles) -> adj
    tc_gemm_kernel<1><<<1056, 256, SMEM_TOTAL2>>>(
        Hh, Hl, Hh, Hl, adj, nullptr, nullptr, nullptr, NN, NN, HTOT, 0.125f);

    // 4) per-row top-30 + softmax (radix select)
    topk_softmax_kernel<<<NN, 256>>>(adj, idx, wv);

    // 5) hidden = x @ W1^T + b1  (single 256-wide tile column)
    tc_gemm_kernel<2><<<dim3(1, NN / 128), 256, SMEM_TOTAL2>>>(
        fXh, fXl, W1h, W1l, hidden, nullptr, nullptr, b1, NN, HID, DD, 1.f);

    // 6) h = relu(adj_sp @ hidden)
    spmm_kernel<1><<<NN, HID>>>(idx, wv, hidden, h, HID);

    // 7) g = h @ W2^T + b2
    gemm_nt_kernel<0, 1><<<dim3(1, NN / 128), 256>>>(h, W2, b2, g, NN, CC, HID);

    // 8) out = adj_sp @ g
    spmm_kernel<0><<<NN, CC>>>(idx, wv, g, out, CC);
}

// round 17
// speedup vs baseline: 1.0284x; 1.0284x over previous
#include <cuda_runtime.h>
#include <cuda_bf16.h>
#include <cstdint>

// Problem dims (fixed by dataset)
#define NN    8192
#define DD    512
#define HTOT  2048   // P*H = 8*256 stacked perspectives
#define HID   256
#define CC    64
#define TOPK  30

using bf16 = __nv_bfloat16;

// tcgen05 is only legal in the compute_103a device pass. The harness also
// compiles a plain sm_103 pass; give it a correct fallback body.
#if defined(__CUDA_ARCH__) && !defined(__CUDA_ARCH_FEAT_SM103_ALL)
#define TC_FALLBACK 1
#else
#define TC_FALLBACK 0
#endif

// -------- scratch (static device globals; no allocation allowed) ----------
// All bf16 GEMM operands live in BLOCKED layout: 64-col blocks, each block
// holding SW128-swizzled 8-row x 128B atoms in smem-image byte order, so a
// K-chunk panel is one contiguous region (bulk-copyable).
__device__ bf16  g_fA_hi[(size_t)NN * DD];
__device__ bf16  g_fA_lo[(size_t)NN * DD];
__device__ bf16  g_fX_hi[(size_t)NN * DD];
__device__ bf16  g_fX_lo[(size_t)NN * DD];
__device__ bf16  g_fW_hi[(size_t)HTOT * DD];
__device__ bf16  g_fW_lo[(size_t)HTOT * DD];
__device__ bf16  g_W1_hi[(size_t)HID * DD];
__device__ bf16  g_W1_lo[(size_t)HID * DD];
__device__ bf16  g_Hh[(size_t)NN * HTOT];
__device__ bf16  g_Hl[(size_t)NN * HTOT];
__device__ float g_hidden[(size_t)NN * HID];
__device__ float g_h[(size_t)NN * HID];
__device__ float g_g[(size_t)NN * CC];
__device__ int   g_idx[(size_t)NN * TOPK];
__device__ float g_w[(size_t)NN * TOPK];

// Blocked-layout byte offset of element (row, col) in an [R x C] bf16 matrix.
// block = col>>6 (stride R*128 bytes); within-block SW128 atom addressing.
__host__ __device__ __forceinline__ uint32_t blk_byte_off(int row, int col, int R) {
    uint32_t boff = (uint32_t)((row >> 3) * 1024 + (row & 7) * 128 + (col & 63) * 2);
    uint32_t sw = boff ^ ((boff >> 3) & 0x70u);
    return (uint32_t)(col >> 6) * (uint32_t)(R * 128) + sw;
}

// ===========================================================================
// PTX helpers
// ===========================================================================
__device__ __forceinline__ uint32_t smem_to_u32(const void* p) {
    uint32_t a;
    asm("{ .reg .u64 t; cvta.to.shared.u64 t, %1; cvt.u32.u64 %0, t; }" : "=r"(a) : "l"(p));
    return a;
}
__device__ __forceinline__ uint32_t elect_one_pred() {
    uint32_t p;
    asm volatile("{ .reg .pred p; elect.sync _|p, 0xFFFFFFFF; selp.b32 %0, 1, 0, p; }" : "=r"(p));
    return p;
}

#define TCGEN05_ALLOC(sa, n) \
    asm volatile("tcgen05.alloc.cta_group::1.sync.aligned.shared::cta.b32 [%0], %1;" \
        :: "r"((uint32_t)(sa)), "r"((uint32_t)(n)) : "memory")
#define TCGEN05_DEALLOC(t, n) \
    asm volatile("tcgen05.dealloc.cta_group::1.sync.aligned.b32 %0, %1;" :: "r"(t), "r"((uint32_t)(n)))
#define TCGEN05_RELINQ() \
    asm volatile("tcgen05.relinquish_alloc_permit.cta_group::1.sync.aligned;")
#define TCGEN05_COMMIT(mb) \
    asm volatile("tcgen05.commit.cta_group::1.mbarrier::arrive::one.shared::cluster.b64 [%0];" \
        :: "r"((uint32_t)(mb)) : "memory")
#define TCGEN05_WAIT_LD()  asm volatile("tcgen05.wait::ld.sync.aligned;" ::: "memory")
#define TCGEN05_FENCE_AFTER()  asm volatile("tcgen05.fence::after_thread_sync;" ::: "memory")
#define TCGEN05_FENCE_BEFORE() asm volatile("tcgen05.fence::before_thread_sync;" ::: "memory")

#define MBARRIER_INIT(mb, c) \
    asm volatile("mbarrier.init.shared.b64 [%0], %1;" :: "r"((uint32_t)(mb)), "r"((uint32_t)(c)) : "memory")
#define MBARRIER_INVAL(mb) \
    asm volatile("mbarrier.inval.shared.b64 [%0];" :: "r"((uint32_t)(mb)) : "memory")
#define MBARRIER_EXPECT_TX(mb, n) \
    asm volatile("mbarrier.arrive.expect_tx.shared.b64 _, [%0], %1;" \
        :: "r"((uint32_t)(mb)), "r"((uint32_t)(n)) : "memory")

#define MBARRIER_WAIT_PARITY(mb, ph) do { \
    uint32_t _mb = (uint32_t)(mb), _ph = (uint32_t)(ph), _done; \
    asm volatile("{ .reg .pred p; mbarrier.try_wait.parity.acquire.cta.shared::cta.b64 p, [%1], %2; selp.b32 %0, 1, 0, p; }" \
        : "=r"(_done) : "r"(_mb), "r"(_ph) : "memory"); \
    if (!_done) { \
        asm volatile("{ .reg .pred P1; WL_%=: mbarrier.try_wait.parity.acquire.cta.shared::cta.b64 P1, [%0], %1, 0x989680; @P1 bra.uni WD_%=; bra.uni WL_%=; WD_%=: }" \
            :: "r"(_mb), "r"(_ph) : "memory"); \
    } } while (0)

// bulk async copy gmem -> smem, completion counted on mbarrier tx
#define BULK_G2S(dst, src, sz, mb) \
    asm volatile("cp.async.bulk.shared::cluster.global.mbarrier::complete_tx::bytes [%0], [%1], %2, [%3];" \
        :: "r"((uint32_t)(dst)), "l"(src), "r"((uint32_t)(sz)), "r"((uint32_t)(mb)) : "memory")

#define TCGEN05_LD_32X32B_X32(r, ta) \
    asm volatile( \
        "tcgen05.ld.sync.aligned.32x32b.x32.b32 " \
        "{%0, %1, %2, %3, %4, %5, %6, %7, " \
        " %8, %9, %10, %11, %12, %13, %14, %15, " \
        " %16, %17, %18, %19, %20, %21, %22, %23, " \
        " %24, %25, %26, %27, %28, %29, %30, %31}, [%32];" \
        : "=r"((r)[0]),  "=r"((r)[1]),  "=r"((r)[2]),  "=r"((r)[3]), \
          "=r"((r)[4]),  "=r"((r)[5]),  "=r"((r)[6]),  "=r"((r)[7]), \
          "=r"((r)[8]),  "=r"((r)[9]),  "=r"((r)[10]), "=r"((r)[11]), \
          "=r"((r)[12]), "=r"((r)[13]), "=r"((r)[14]), "=r"((r)[15]), \
          "=r"((r)[16]), "=r"((r)[17]), "=r"((r)[18]), "=r"((r)[19]), \
          "=r"((r)[20]), "=r"((r)[21]), "=r"((r)[22]), "=r"((r)[23]), \
          "=r"((r)[24]), "=r"((r)[25]), "=r"((r)[26]), "=r"((r)[27]), \
          "=r"((r)[28]), "=r"((r)[29]), "=r"((r)[30]), "=r"((r)[31]) \
        : "r"(ta))

// SW128 smem descriptor: layout=SW128(2), version=1(Blackwell), SBO=64, LBO=1
static constexpr uint64_t SMEM_DESC_BASE_SW128 =
    (uint64_t(2) << 61) | (uint64_t(1) << 46) | (uint64_t(64) << 32) | (uint64_t(1) << 16);
#define MAKE_SMEM_DESC(a) (SMEM_DESC_BASE_SW128 | ((uint64_t)((a) >> 4) & 0x3FFF))

#if !TC_FALLBACK
// SS bf16 MMA, cta_group::1, fp32 accumulate
__device__ __forceinline__ void mma_bf16_ss_cg1(uint32_t d, uint64_t ad, uint64_t bd,
                                                uint32_t idesc, bool accum) {
    uint32_t en = accum ? 1u : 0u;
    asm volatile(
        "{\n\t.reg .pred p;\n\tsetp.ne.u32 p, %5, 0;\n\t"
        "tcgen05.mma.cta_group::1.kind::f16 [%0], %1, %2, %3, {%4, %4, %4, %4}, p;\n\t}"
        :: "r"(d), "l"(ad), "l"(bd), "r"(idesc), "r"(0u), "r"(en) : "memory");
}
#endif

// ===========================================================================
// fused dual fp32 -> (bf16 hi, bf16 lo) split, BLOCKED output (C=512 inputs)
// ===========================================================================
__device__ __forceinline__ void split_body_blk(const float* __restrict__ in,
                                               bf16* __restrict__ hi, bf16* __restrict__ lo,
                                               int i, int R)
{
    float4 v = *(const float4*)(in + i);
    float vv[4] = {v.x, v.y, v.z, v.w};
    bf16 h[4], l[4];
#pragma unroll
    for (int j = 0; j < 4; j++) {
        bf16 hh = __float2bfloat16(vv[j]);
        h[j] = hh;
        l[j] = __float2bfloat16(vv[j] - __bfloat162float(hh));
    }
    int row = i >> 9, col = i & 511;          // all split inputs have C = 512
    uint32_t bo = blk_byte_off(row, col, R);
    *(uint2*)((char*)hi + bo) = *(uint2*)h;
    *(uint2*)((char*)lo + bo) = *(uint2*)l;
}

__global__ void split2_kernel(const float* __restrict__ in1, bf16* __restrict__ hi1,
                              bf16* __restrict__ lo1, int n1, int R1,
                              const float* __restrict__ in2, bf16* __restrict__ hi2,
                              bf16* __restrict__ lo2, int n2, int R2)
{
    int i = (blockIdx.x * blockDim.x + threadIdx.x) * 4;
    if (i < n1) { split_body_blk(in1, hi1, lo1, i, R1); return; }
    i -= n1;
    if (i < n2) split_body_blk(in2, hi2, lo2, i, R2);
}

// ===========================================================================
// tcgen05 bf16x3 NT GEMM, 128x256 tile, K-chunk 64, BULK-copy loads,
// single-stage, 2 CTAs/SM, single-thread mainloop (no per-chunk barriers).
// Operands A/B in blocked layout (row counts RA, RB). 
// MODE 0: C = relu(A B^T), output split to bf16 hi/lo BLOCKED (R=NN)
// MODE 1: syrk tiles (bi <= 2*bj+1), C = scale*A A^T fp32 row-major
// MODE 2: C = A B^T + bias, fp32 row-major
// ===========================================================================
#define KCC   64
#define NT    256
#define STAGE 98304          // Ah 16K | Al 16K | Bh 32K | Bl 32K
#define OFF_AH 0
#define OFF_AL 16384
#define OFF_BH 32768
#define OFF_BL 65536
#define SMEM_TOTAL2 (1024 + STAGE)
// idesc: dtype F32, atype/btype BF16, N=256 (32<<17), M=128 (8<<24)
#define TC_IDESC2 ((1u << 4) | (1u << 7) | (1u << 10) | (32u << 17) | (8u << 24))

template<int MODE>
__global__ __launch_bounds__(256, 2)
void tc_gemm_kernel(const bf16* __restrict__ Ah, const bf16* __restrict__ Al,
                    const bf16* __restrict__ Bh, const bf16* __restrict__ Bl,
                    float* __restrict__ Cf, bf16* __restrict__ Chi, bf16* __restrict__ Clo,
                    const float* __restrict__ bias,
                    int Mdim, int Ndim, int Kdim, int RA, int RB, float scale)
{
    extern __shared__ char smem[];
    const int tid = threadIdx.x;

    int bm, bn, bi = 0, bj = 0;
    if (MODE == 1) {
        int t = blockIdx.x;
        for (;;) {
            int cnt = 2 * bj + 2; if (cnt > 64) cnt = 64;
            if (t < cnt) break;
            t -= cnt; bj++;
        }
        bi = t;
        bm = bi * 128; bn = bj * NT;
    } else {
        bm = blockIdx.y * 128; bn = blockIdx.x * NT;
    }

#if TC_FALLBACK
    // ------- plain-sm_103 pass: correct, slow FFMA path (dead code on GB300) ---
    (void)smem;
    const bool straddle = (MODE == 1) && (bi >= 2 * bj);
    const int tm = (tid >> 4) << 3;
    const int tnb = (tid & 15) << 3;
    for (int nh = 0; nh < 2; nh++) {
        int tn = nh * 128 + tnb;
        float acc[8][8];
#pragma unroll
        for (int i = 0; i < 8; i++)
#pragma unroll
            for (int j = 0; j < 8; j++) acc[i][j] = 0.f;
        for (int k = 0; k < Kdim; k++) {
            float a[8], b[8];
#pragma unroll
            for (int i = 0; i < 8; i++) {
                uint32_t o = blk_byte_off(bm + tm + i, k, RA);
                a[i] = __bfloat162float(*(const bf16*)((const char*)Ah + o))
                     + __bfloat162float(*(const bf16*)((const char*)Al + o));
            }
#pragma unroll
            for (int j = 0; j < 8; j++) {
                uint32_t o = blk_byte_off(bn + tn + j, k, RB);
                b[j] = __bfloat162float(*(const bf16*)((const char*)Bh + o))
                     + __bfloat162float(*(const bf16*)((const char*)Bl + o));
            }
#pragma unroll
            for (int i = 0; i < 8; i++)
#pragma unroll
                for (int j = 0; j < 8; j++)
                    acc[i][j] = fmaf(a[i], b[j], acc[i][j]);
        }
#pragma unroll
        for (int i = 0; i < 8; i++) {
            int gr = bm + tm + i;
#pragma unroll
            for (int j = 0; j < 8; j++) {
                int gc = bn + tn + j;
                float v = acc[i][j];
                if (MODE == 0) {
                    v = fmaxf(v, 0.f);
                    bf16 hh = __float2bfloat16(v);
                    uint32_t o = blk_byte_off(gr, gc, NN);
                    *(bf16*)((char*)Chi + o) = hh;
                    *(bf16*)((char*)Clo + o) = __float2bfloat16(v - __bfloat162float(hh));
                } else if (MODE == 2) {
                    Cf[(size_t)gr * Ndim + gc] = v + bias[gc];
                } else {
                    v *= scale;
                    if (!straddle || gc >= gr) Cf[(size_t)gr * Ndim + gc] = v;
                    if (gc > gr)               Cf[(size_t)gc * Ndim + gr] = v;
                }
            }
        }
    }
#else
    // ------- sm_103a pass: tcgen05 bf16x3, bulk loads, 1-thread mainloop -------
    const uint32_t sb = smem_to_u32(smem);
    const int wid = tid >> 5;
    const int lid = tid & 31;

    if (wid == 0) {
        TCGEN05_ALLOC(sb + 0, 256);
        TCGEN05_RELINQ();          // free permit immediately (R13 fix)
    }
    if (tid == 0) { MBARRIER_INIT(sb + 8, 1); MBARRIER_INIT(sb + 16, 1); }
    __syncthreads();
    uint32_t tmem;
    asm volatile("ld.shared.b32 %0, [%1];" : "=r"(tmem) : "r"(sb));

    const uint32_t st = sb + 1024;
    const uint64_t dAh = MAKE_SMEM_DESC(st + OFF_AH);
    const uint64_t dAl = MAKE_SMEM_DESC(st + OFF_AL);
    const uint64_t dBh = MAKE_SMEM_DESC(st + OFF_BH);
    const uint64_t dBl = MAKE_SMEM_DESC(st + OFF_BL);

    // chunk c of a blocked matrix = contiguous region at c*R*128 + row0*128
    const char* pAh = (const char*)Ah + (size_t)bm * 128;
    const char* pAl = (const char*)Al + (size_t)bm * 128;
    const char* pBh = (const char*)Bh + (size_t)bn * 128;
    const char* pBl = (const char*)Bl + (size_t)bn * 128;
    const size_t sA = (size_t)RA * 128;
    const size_t sB = (size_t)RB * 128;
    const int nc = Kdim / KCC;

    if (wid == 0 && elect_one_pred()) {
        int phF = 0, phD = 0;
        for (int c = 0; c < nc; c++) {
            if (c) { MBARRIER_WAIT_PARITY(sb + 16, phD); phD ^= 1; }  // MMAs of c-1 done
            MBARRIER_EXPECT_TX(sb + 8, STAGE);
            BULK_G2S(st + OFF_AH, pAh + (size_t)c * sA, 16384, sb + 8);
            BULK_G2S(st + OFF_AL, pAl + (size_t)c * sA, 16384, sb + 8);
            BULK_G2S(st + OFF_BH, pBh + (size_t)c * sB, 32768, sb + 8);
            BULK_G2S(st + OFF_BL, pBl + (size_t)c * sB, 32768, sb + 8);
            MBARRIER_WAIT_PARITY(sb + 8, phF); phF ^= 1;               // loads landed
#pragma unroll
            for (int ks = 0; ks < 4; ks++) {
                const uint64_t off = 2 * ks;        // K16 steps within atom-column
                mma_bf16_ss_cg1(tmem, dAh + off, dBh + off, TC_IDESC2, !(c == 0 && ks == 0));
                mma_bf16_ss_cg1(tmem, dAh + off, dBl + off, TC_IDESC2, true);
                mma_bf16_ss_cg1(tmem, dAl + off, dBh + off, TC_IDESC2, true);
            }
            TCGEN05_COMMIT(sb + 16);
        }
        MBARRIER_WAIT_PARITY(sb + 16, phD);                            // last MMAs done
    }
    __syncthreads();
    TCGEN05_FENCE_AFTER();

    // Epilogue: warps 0-3 read the 128x256 fp32 accumulator (lane = M-row)
    if (wid < 4) {
        const int row = bm + wid * 32 + lid;
        const bool straddle = (MODE == 1) && (bi >= 2 * bj);
#pragma unroll
        for (int cb = 0; cb < 8; cb++) {
            uint32_t r[32];
            TCGEN05_LD_32X32B_X32(r, tmem + cb * 32);
            TCGEN05_WAIT_LD();
            const int colb = bn + cb * 32;
            if (MODE == 0) {
#pragma unroll
                for (int c8 = 0; c8 < 4; c8++) {
                    bf16 hs[8], ls[8];
#pragma unroll
                    for (int j = 0; j < 8; j++) {
                        float v = fmaxf(__uint_as_float(r[c8 * 8 + j]), 0.f);
                        bf16 hh = __float2bfloat16(v);
                        hs[j] = hh;
                        ls[j] = __float2bfloat16(v - __bfloat162float(hh));
                    }
                    uint32_t o = blk_byte_off(row, colb + c8 * 8, NN);  // blocked out
                    *(uint4*)((char*)Chi + o) = *(uint4*)hs;
                    *(uint4*)((char*)Clo + o) = *(uint4*)ls;
                }
            } else if (MODE == 2) {
#pragma unroll
                for (int q = 0; q < 8; q++) {
                    float4 o;
                    o.x = __uint_as_float(r[q * 4 + 0]) + bias[colb + q * 4 + 0];
                    o.y = __uint_as_float(r[q * 4 + 1]) + bias[colb + q * 4 + 1];
                    o.z = __uint_as_float(r[q * 4 + 2]) + bias[colb + q * 4 + 2];
                    o.w = __uint_as_float(r[q * 4 + 3]) + bias[colb + q * 4 + 3];
                    *(float4*)(Cf + (size_t)row * Ndim + colb + q * 4) = o;
                }
            } else {
                float vs[32];
#pragma unroll
                for (int c = 0; c < 32; c++) vs[c] = __uint_as_float(r[c]) * scale;
                if (!straddle) {
                    float* dst = Cf + (size_t)row * Ndim + colb;
#pragma unroll
                    for (int q = 0; q < 8; q++)
                        *(float4*)(dst + q * 4) =
                            make_float4(vs[q * 4], vs[q * 4 + 1], vs[q * 4 + 2], vs[q * 4 + 3]);
#pragma unroll
                    for (int c = 0; c < 32; c++)
                        Cf[(size_t)(colb + c) * Ndim + row] = vs[c];
                } else {
#pragma unroll
                    for (int c = 0; c < 32; c++) {
                        const int gc = colb + c;
                        if (gc >= row) Cf[(size_t)row * Ndim + gc] = vs[c];
                        if (gc > row)  Cf[(size_t)gc * Ndim + row] = vs[c];
                    }
                }
            }
        }
        TCGEN05_FENCE_BEFORE();
    }
    __syncthreads();
    if (tid == 0) { MBARRIER_INVAL(sb + 8); MBARRIER_INVAL(sb + 16); }
    __syncthreads();
    if (wid == 0) TCGEN05_DEALLOC(tmem, 256);
#endif
}

// ===========================================================================
// SIMT fp32 NT GEMM (kept for the tiny h @ W2^T + b2)
// ===========================================================================
#define TILE 128
#define KT   16
#define SPITCH 130
template<int RELU, int BIAS>
__global__ __launch_bounds__(256)
void gemm_nt_kernel(const float* __restrict__ A, const float* __restrict__ B,
                    const float* __restrict__ bias, float* __restrict__ C,
                    int M, int N, int K)
{
    __shared__ float As[KT][SPITCH];
    __shared__ float Bs[KT][SPITCH];
    const int tid = threadIdx.x;
    const int bm = blockIdx.y * TILE;
    const int bn = blockIdx.x * TILE;
    const int tm = (tid >> 4) << 3;
    const int tn = (tid & 15) << 3;

    float acc[8][8];
#pragma unroll
    for (int i = 0; i < 8; i++)
#pragma unroll
        for (int j = 0; j < 8; j++) acc[i][j] = 0.f;

    const int lrow  = tid >> 1;
    const int lhalf = (tid & 1) * 8;

    for (int k0 = 0; k0 < K; k0 += KT) {
        {
            int gr = bm + lrow;
            float4 v0 = make_float4(0, 0, 0, 0), v1 = v0;
            if (gr < M) {
                const float* src = A + (size_t)gr * K + k0 + lhalf;
                v0 = *(const float4*)src; v1 = *(const float4*)(src + 4);
            }
            As[lhalf+0][lrow]=v0.x; As[lhalf+1][lrow]=v0.y;
            As[lhalf+2][lrow]=v0.z; As[lhalf+3][lrow]=v0.w;
            As[lhalf+4][lrow]=v1.x; As[lhalf+5][lrow]=v1.y;
            As[lhalf+6][lrow]=v1.z; As[lhalf+7][lrow]=v1.w;
        }
        {
            int gr = bn + lrow;
            float4 v0 = make_float4(0, 0, 0, 0), v1 = v0;
            if (gr < N) {
                const float* src = B + (size_t)gr * K + k0 + lhalf;
                v0 = *(const float4*)src; v1 = *(const float4*)(src + 4);
            }
            Bs[lhalf+0][lrow]=v0.x; Bs[lhalf+1][lrow]=v0.y;
            Bs[lhalf+2][lrow]=v0.z; Bs[lhalf+3][lrow]=v0.w;
            Bs[lhalf+4][lrow]=v1.x; Bs[lhalf+5][lrow]=v1.y;
            Bs[lhalf+6][lrow]=v1.z; Bs[lhalf+7][lrow]=v1.w;
        }
        __syncthreads();
#pragma unroll
        for (int kk = 0; kk < KT; kk++) {
            float a[8], b[8];
#pragma unroll
            for (int i = 0; i < 8; i++) a[i] = As[kk][tm + i];
#pragma unroll
            for (int j = 0; j < 8; j++) b[j] = Bs[kk][tn + j];
#pragma unroll
            for (int i = 0; i < 8; i++)
#pragma unroll
                for (int j = 0; j < 8; j++)
                    acc[i][j] = fmaf(a[i], b[j], acc[i][j]);
        }
        __syncthreads();
    }
#pragma unroll
    for (int i = 0; i < 8; i++) {
        int gr = bm + tm + i;
        if (gr >= M) break;
#pragma unroll
        for (int j = 0; j < 8; j++) {
            int gc = bn + tn + j;
            if (gc < N) {
                float v = acc[i][j];
                if (BIAS) v += bias[gc];
                if (RELU) v = fmaxf(v, 0.f);
                C[(size_t)gr * N + gc] = v;
            }
        }
    }
}

// ===========================================================================
// Per-row top-30 + softmax via 4-round radix select (proven R11)
// ===========================================================================
__global__ __launch_bounds__(256)
void topk_softmax_kernel(float* __restrict__ adj,
                         int* __restrict__ oidx, float* __restrict__ ow)
{
    const int row = blockIdx.x;
    const int tid = threadIdx.x;
    float* rp = adj + (size_t)row * NN;

    uint32_t u[32];
#pragma unroll
    for (int i = 0; i < 32; i++) {
        uint32_t b = __float_as_uint(rp[tid + 256 * i]);
        u[i] = (b & 0x80000000u) ? ~b : (b | 0x80000000u);
    }

    __shared__ uint32_t hist[256];
    __shared__ uint32_t sS[256];
    __shared__ uint32_t sb_sel, sAboveSh;
    __shared__ int swin, snsel;
    __shared__ int   scol[TOPK];
    __shared__ float sval[TOPK];
    __shared__ int   warpmin[8];
    __shared__ float se[32];
    __shared__ float sinv;

    uint32_t pref = 0;
    uint32_t above = 0;
    int shift = 24;

#pragma unroll
    for (int round = 0; round < 4; round++) {
        hist[tid] = 0;
        __syncthreads();
        if (round == 0) {
#pragma unroll
            for (int i = 0; i < 32; i++)
                atomicAdd(&hist[u[i] >> 24], 1u);
        } else {
            const uint32_t mask = 0xFFFFFFFFu << (shift + 8);
#pragma unroll
            for (int i = 0; i < 32; i++)
                if ((u[i] & mask) == pref)
                    atomicAdd(&hist[(u[i] >> shift) & 255u], 1u);
        }
        __syncthreads();
        sS[tid] = hist[tid];
        for (int off = 1; off < 256; off <<= 1) {
            __syncthreads();
            uint32_t t = (tid + off < 256) ? sS[tid + off] : 0u;
            __syncthreads();
            sS[tid] += t;
        }
        __syncthreads();
        {
            uint32_t gt = above + ((tid < 255) ? sS[tid + 1] : 0u);
            uint32_t ge = above + sS[tid];
            if (gt < TOPK && ge >= TOPK) { sb_sel = (uint32_t)tid; sAboveSh = gt; }
        }
        __syncthreads();
        pref |= sb_sel << shift;
        above = sAboveSh;
        shift -= 8;
        __syncthreads();
    }

    const uint32_t T = pref;
    const int tcount = TOPK - (int)above;
    uint32_t tb = (T & 0x80000000u) ? (T ^ 0x80000000u) : ~T;
    const float Tf = __uint_as_float(tb);

    if (tid == 0) snsel = 0;
    __syncthreads();
#pragma unroll
    for (int i = 0; i < 32; i++) {
        if (u[i] > T) {
            int s = atomicAdd(&snsel, 1);
            scol[s] = tid + 256 * i;
            uint32_t k = u[i];
            uint32_t vb = (k & 0x80000000u) ? (k ^ 0x80000000u) : ~k;
            sval[s] = __uint_as_float(vb);
        }
    }
    __syncthreads();

    uint32_t takenMask = 0;
    for (int t = 0; t < tcount; t++) {
        int mc = 0x7FFFFFFF;
#pragma unroll
        for (int i = 0; i < 32; i++)
            if (u[i] == T && !(takenMask & (1u << i))) {
                int c = tid + 256 * i;
                if (c < mc) mc = c;
            }
#pragma unroll
        for (int s = 16; s; s >>= 1) {
            int o = __shfl_down_sync(0xFFFFFFFFu, mc, s);
            if (o < mc) mc = o;
        }
        if ((tid & 31) == 0) warpmin[tid >> 5] = mc;
        __syncthreads();
        if (tid == 0) {
            int m = warpmin[0];
#pragma unroll
            for (int w = 1; w < 8; w++) if (warpmin[w] < m) m = warpmin[w];
            swin = m;
            int s = snsel;
            scol[s] = m; sval[s] = Tf; snsel = s + 1;
        }
        __syncthreads();
        int w = swin;
        if ((w & 255) == tid) takenMask |= 1u << (w >> 8);
    }
    __syncthreads();

    if (tid < 32) {
        float v = (tid < TOPK) ? sval[tid] : -3.4e38f;
        float m = v;
#pragma unroll
        for (int s = 16; s; s >>= 1) m = fmaxf(m, __shfl_xor_sync(0xFFFFFFFFu, m, s));
        float e = (tid < TOPK) ? expf(v - m) : 0.f;
        se[tid] = e;
#pragma unroll
        for (int s = 16; s; s >>= 1) e += __shfl_down_sync(0xFFFFFFFFu, e, s);
        if (tid == 0) sinv = 1.f / e;
    }
    __syncthreads();

    float4 z = make_float4(0.f, 0.f, 0.f, 0.f);
    float4* rp4 = (float4*)rp;
#pragma unroll
    for (int i = 0; i < 8; i++) rp4[tid + 256 * i] = z;
    __syncthreads();
    if (tid < TOPK) {
        float wv = se[tid] * sinv;
        rp[scol[tid]] = wv;
        oidx[(size_t)row * TOPK + tid] = scol[tid];
        ow[(size_t)row * TOPK + tid] = wv;
    }
}

// ===========================================================================
// Sparse adj @ M
// ===========================================================================
template<int RELU>
__global__ void spmm_kernel(const int* __restrict__ idx, const float* __restrict__ w,
                            const float* __restrict__ Min, float* __restrict__ Mout,
                            int ncols)
{
    const int row = blockIdx.x;
    const int j = threadIdx.x;
    const int*   ip = idx + (size_t)row * TOPK;
    const float* wp = w   + (size_t)row * TOPK;
    float acc = 0.f;
#pragma unroll
    for (int k = 0; k < TOPK; k++)
        acc = fmaf(wp[k], Min[(size_t)ip[k] * ncols + j], acc);
    if (RELU) acc = fmaxf(acc, 0.f);
    Mout[(size_t)row * ncols + j] = acc;
}

// ===========================================================================
extern "C" void kernel_launch(void* const* d_in, const int* in_sizes, int n_in,
                              void* d_out, int out_size)
{
    const float* features = (const float*)d_in[0];
    const float* x        = (const float*)d_in[1];
    const float* W_sims   = (const float*)d_in[2];
    const float* W1       = (const float*)d_in[3];
    const float* b1       = (const float*)d_in[4];
    const float* W2       = (const float*)d_in[5];
    const float* b2       = (const float*)d_in[6];

    float* out = (float*)d_out;
    float* adj = out + (size_t)NN * CC;

    bf16 *fAh, *fAl, *fXh, *fXl, *fWh, *fWl, *W1h, *W1l, *Hh, *Hl;
    float *hidden, *h, *g, *wv; int* idx;
    cudaGetSymbolAddress((void**)&fAh, g_fA_hi);  cudaGetSymbolAddress((void**)&fAl, g_fA_lo);
    cudaGetSymbolAddress((void**)&fXh, g_fX_hi);  cudaGetSymbolAddress((void**)&fXl, g_fX_lo);
    cudaGetSymbolAddress((void**)&fWh, g_fW_hi);  cudaGetSymbolAddress((void**)&fWl, g_fW_lo);
    cudaGetSymbolAddress((void**)&W1h, g_W1_hi);  cudaGetSymbolAddress((void**)&W1l, g_W1_lo);
    cudaGetSymbolAddress((void**)&Hh,  g_Hh);     cudaGetSymbolAddress((void**)&Hl,  g_Hl);
    cudaGetSymbolAddress((void**)&hidden, g_hidden);
    cudaGetSymbolAddress((void**)&h,  g_h);
    cudaGetSymbolAddress((void**)&g,  g_g);
    cudaGetSymbolAddress((void**)&wv, g_w);
    cudaGetSymbolAddress((void**)&idx, g_idx);

    cudaFuncSetAttribute(tc_gemm_kernel<0>, cudaFuncAttributeMaxDynamicSharedMemorySize, SMEM_TOTAL2);
    cudaFuncSetAttribute(tc_gemm_kernel<1>, cudaFuncAttributeMaxDynamicSharedMemorySize, SMEM_TOTAL2);
    cudaFuncSetAttribute(tc_gemm_kernel<2>, cudaFuncAttributeMaxDynamicSharedMemorySize, SMEM_TOTAL2);

    // Launch order puts the SYRK at our 4th launch (ncu -s 5 lands on it).

    // 0) fused split: features + W_sims -> blocked bf16 hi/lo
    {
        int n1 = NN * DD, n2 = HTOT * DD;
        split2_kernel<<<((n1 + n2) / 4 + 255) / 256, 256>>>(
            features, fAh, fAl, n1, NN, W_sims, fWh, fWl, n2, HTOT);
    }

    // 1) Hc = relu(X @ W_all^T) -> blocked bf16 hi/lo  [8192, 2048]
    tc_gemm_kernel<0><<<dim3(HTOT / NT, NN / 128), 256, SMEM_TOTAL2>>>(
        fAh, fAl, fWh, fWl, nullptr, Hh, Hl, nullptr, NN, HTOT, DD, NN, HTOT, 1.f);

    // 2) fused split: x + W1 (independent; placed here so syrk is 4th)
    {
        int n1 = NN * DD, n2 = HID * DD;
        split2_kernel<<<((n1 + n2) / 4 + 255) / 256, 256>>>(
            x, fXh, fXl, n1, NN, W1, W1h, W1l, n2, HID);
    }

    // 3) att = Hc Hc^T / 8  (128x256 tiles, bi<=2bj+1; 1056 tiles) -> adj
    tc_gemm_kernel<1><<<1056, 256, SMEM_TOTAL2>>>(
        Hh, Hl, Hh, Hl, adj, nullptr, nullptr, nullptr, NN, NN, HTOT, NN, NN, 0.125f);

    // 4) per-row top-30 + softmax (radix select)
    topk_softmax_kernel<<<NN, 256>>>(adj, idx, wv);

    // 5) hidden = x @ W1^T + b1  (single 256-wide tile column)
    tc_gemm_kernel<2><<<dim3(1, NN / 128), 256, SMEM_TOTAL2>>>(
        fXh, fXl, W1h, W1l, hidden, nullptr, nullptr, b1, NN, HID, DD, NN, HID, 1.f);

    // 6) h = relu(adj_sp @ hidden)
    spmm_kernel<1><<<NN, HID>>>(idx, wv, hidden, h, HID);

    // 7) g = h @ W2^T + b2
    gemm_nt_kernel<0, 1><<<dim3(1, NN / 128), 256>>>(h, W2, b2, g, NN, CC, HID);

    // 8) out = adj_sp @ g
    spmm_kernel<0><<<NN, CC>>>(idx, wv, g, out, CC);
}